// round 5
// baseline (speedup 1.0000x reference)
#include <cuda_runtime.h>
#include <math_constants.h>

// Problem constants (fixed by the reference)
#define BB 64
#define PP 8732
#define CC 81
#define NPRI (BB * PP)          // 558848 priors total
#define WPB 16                  // warps per block in main kernel
#define TPB1 (WPB * 32)         // 512 threads
#define GRID1 (NPRI / WPB)      // 34928 blocks (exact)

// ---------------- scratch (no allocations allowed) ----------------
__device__ float g_ce[NPRI];          // per-prior CE loss
__device__ float g_loc_part[GRID1];   // per-block partial smooth-L1 loc sums
__device__ float g_fc_part[GRID1];    // per-block partial smooth-L1 four-corner sums
__device__ float g_loss_c;            // mined confidence loss (summed across batches)
__device__ int   g_num_pos;           // total positives (N)

// ---------------- kernel 0: zero accumulators ----------------
__global__ void k_zero() {
    g_loss_c = 0.0f;
    g_num_pos = 0;
}

__device__ __forceinline__ float smooth_l1(float a, float b) {
    float d = fabsf(a - b);
    return (d < 1.0f) ? 0.5f * d * d : d - 0.5f;
}

// ---------------- kernel 1: per-prior CE + masked smooth-L1 ----------------
// One warp per prior. conf row = 81 contiguous fp32 -> 3 coalesced loads/lane.
__global__ __launch_bounds__(TPB1) void k_main(
    const float* __restrict__ loc,
    const float* __restrict__ conf,
    const float* __restrict__ fc,
    const float* __restrict__ loc_t,
    const float* __restrict__ fc_t,
    const int*   __restrict__ conf_t)
{
    __shared__ float s_loc, s_fc;
    if (threadIdx.x == 0) { s_loc = 0.0f; s_fc = 0.0f; }
    __syncthreads();

    const int lane = threadIdx.x & 31;
    const int wid_in_blk = threadIdx.x >> 5;
    const int g = blockIdx.x * WPB + wid_in_blk;   // prior index, exact coverage

    const long long base = (long long)g * CC;

    // load 81 class scores across the warp
    float x0 = conf[base + lane];
    float x1 = conf[base + 32 + lane];
    float x2 = (lane < CC - 64) ? conf[base + 64 + lane] : -CUDART_INF_F;

    // warp max (all lanes)
    float mx = fmaxf(fmaxf(x0, x1), x2);
    #pragma unroll
    for (int o = 16; o > 0; o >>= 1)
        mx = fmaxf(mx, __shfl_xor_sync(0xffffffffu, mx, o));

    // sum of exp(x - mx) via MUFU.EX2
    const float L2E = 1.4426950408889634f;
    float s = exp2f((x0 - mx) * L2E) + exp2f((x1 - mx) * L2E) + exp2f((x2 - mx) * L2E);
    #pragma unroll
    for (int o = 16; o > 0; o >>= 1)
        s += __shfl_xor_sync(0xffffffffu, s, o);

    const int t = conf_t[g];            // uniform address within warp -> broadcast
    const bool pos = (t > 0);

    // smooth-L1 terms on lanes 0-3 (loc) and 0-7 (four corners), masked by pos
    float lv = 0.0f, fv = 0.0f;
    if (pos) {
        if (lane < 4) {
            long long i4 = (long long)g * 4 + lane;
            lv = smooth_l1(loc[i4], loc_t[i4]);
        }
        if (lane < 8) {
            long long i8 = (long long)g * 8 + lane;
            fv = smooth_l1(fc[i8], fc_t[i8]);
        }
    }
    lv += __shfl_xor_sync(0xffffffffu, lv, 1);
    lv += __shfl_xor_sync(0xffffffffu, lv, 2);
    fv += __shfl_xor_sync(0xffffffffu, fv, 1);
    fv += __shfl_xor_sync(0xffffffffu, fv, 2);
    fv += __shfl_xor_sync(0xffffffffu, fv, 4);

    if (lane == 0) {
        const float LN2 = 0.6931471805599453f;
        float lse = mx + LN2 * log2f(s);
        float ce = lse - conf[base + t];   // row is L1-hot
        g_ce[g] = ce;
        atomicAdd(&s_loc, lv);
        atomicAdd(&s_fc, fv);
    }
    __syncthreads();
    if (threadIdx.x == 0) {
        g_loc_part[blockIdx.x] = s_loc;
        g_fc_part[blockIdx.x] = s_fc;
    }
}

// ---------------- kernel 2: per-batch hard-negative mining ----------------
// One block per batch. ce >= 0 always, positives mine as 0, so zero-valued items
// rank after all value>0 items. If num_neg >= m (#negatives with ce>0), the
// selected set's CE-sum equals the full batch CE-sum (zero-CE selections add 0).
// Exact O(m^2) counting fallback otherwise (tie-break by index, matching stable argsort).
#define TPB2 256
__global__ __launch_bounds__(TPB2) void k_mine(const int* __restrict__ conf_t)
{
    const int b = blockIdx.x;
    const int tid = threadIdx.x;
    const long long boff = (long long)b * PP;

    int np = 0, mm = 0;
    float sa = 0.0f, sp = 0.0f;
    for (int p = tid; p < PP; p += TPB2) {
        int t = conf_t[boff + p];
        float ce = g_ce[boff + p];
        bool pos = (t > 0);
        sa += ce;
        if (pos) { np++; sp += ce; }
        else if (ce > 0.0f) mm++;
    }

    __shared__ float r_sa[TPB2], r_sp[TPB2];
    __shared__ int   r_np[TPB2], r_mm[TPB2];
    r_sa[tid] = sa; r_sp[tid] = sp; r_np[tid] = np; r_mm[tid] = mm;
    __syncthreads();
    for (int o = TPB2 / 2; o > 0; o >>= 1) {
        if (tid < o) {
            r_sa[tid] += r_sa[tid + o];
            r_sp[tid] += r_sp[tid + o];
            r_np[tid] += r_np[tid + o];
            r_mm[tid] += r_mm[tid + o];
        }
        __syncthreads();
    }

    __shared__ int s_fallback, s_num_neg;
    if (tid == 0) {
        int num_pos = r_np[0];
        long long nn = (long long)3 * num_pos;
        int num_neg = (nn < (PP - 1)) ? (int)nn : (PP - 1);
        s_num_neg = num_neg;
        atomicAdd(&g_num_pos, num_pos);
        if (num_neg >= r_mm[0]) {
            atomicAdd(&g_loss_c, r_sa[0]);   // all CE>0 negatives selected
            s_fallback = 0;
        } else {
            s_fallback = 1;
        }
    }
    __syncthreads();

    if (s_fallback) {
        // exact top-num_neg selection among CE>0 negatives, stable-index tiebreak
        const int num_neg = s_num_neg;
        float add = 0.0f;
        for (int i = tid; i < PP; i += TPB2) {
            int ti = conf_t[boff + i];
            float ci = g_ce[boff + i];
            if (ti > 0 || !(ci > 0.0f)) continue;
            int rank = 0;
            for (int j = 0; j < PP; j++) {
                int tj = conf_t[boff + j];
                float cj = g_ce[boff + j];
                if (tj <= 0 && cj > 0.0f &&
                    (cj > ci || (cj == ci && j < i))) rank++;
            }
            if (rank < num_neg) add += ci;
        }
        r_sa[tid] = add;
        __syncthreads();
        for (int o = TPB2 / 2; o > 0; o >>= 1) {
            if (tid < o) r_sa[tid] += r_sa[tid + o];
            __syncthreads();
        }
        if (tid == 0) atomicAdd(&g_loss_c, r_sp[0] + r_sa[0]);
    }
}

// ---------------- kernel 3: reduce partials, write 3 outputs ----------------
#define TPB3 256
__global__ __launch_bounds__(TPB3) void k_final(float* __restrict__ out)
{
    const int tid = threadIdx.x;
    float sl = 0.0f, sf = 0.0f;
    for (int i = tid; i < GRID1; i += TPB3) {
        sl += g_loc_part[i];
        sf += g_fc_part[i];
    }
    __shared__ float r_l[TPB3], r_f[TPB3];
    r_l[tid] = sl; r_f[tid] = sf;
    __syncthreads();
    for (int o = TPB3 / 2; o > 0; o >>= 1) {
        if (tid < o) { r_l[tid] += r_l[tid + o]; r_f[tid] += r_f[tid + o]; }
        __syncthreads();
    }
    if (tid == 0) {
        float N = (float)g_num_pos;
        out[0] = r_l[0] / N;      // loss_l / N
        out[1] = g_loss_c / N;    // loss_c / N
        out[2] = r_f[0] / N;      // loss_four_corners / N
    }
}

extern "C" void kernel_launch(void* const* d_in, const int* in_sizes, int n_in,
                              void* d_out, int out_size) {
    const float* loc    = (const float*)d_in[0];
    const float* conf   = (const float*)d_in[1];
    const float* fc     = (const float*)d_in[2];
    const float* loc_t  = (const float*)d_in[3];
    const float* fc_t   = (const float*)d_in[4];
    const int*   conf_t = (const int*)d_in[5];
    float* out = (float*)d_out;

    k_zero<<<1, 1>>>();
    k_main<<<GRID1, TPB1>>>(loc, conf, fc, loc_t, fc_t, conf_t);
    k_mine<<<BB, TPB2>>>(conf_t);
    k_final<<<1, TPB3>>>(out);
}